// round 4
// baseline (speedup 1.0000x reference)
#include <cuda_runtime.h>

#define MAX_BLOCKS 4096
#define NTHREADS 256
#define GRID_BLOCKS (148 * 8)

// Per-block partials {iou_sum, valid_cnt}; overwritten every launch.
__device__ float2 g_part[MAX_BLOCKS];
// Completion counter; atomicInc wraps to 0 after the last block -> self-resetting.
__device__ unsigned int g_count;

__device__ __forceinline__ void iou_accum(const float4 p, const float4 t,
                                          float& lsum, float& lcnt) {
    // half-extents
    float phw = p.z * 0.5f, phh = p.w * 0.5f;
    float thw = t.z * 0.5f, thh = t.w * 0.5f;

    float ix = fminf(p.x + phw, t.x + thw) - fmaxf(p.x - phw, t.x - thw);
    float iy = fminf(p.y + phh, t.y + thh) - fmaxf(p.y - phh, t.y - thh);
    float inter = fmaxf(ix, 0.0f) * fmaxf(iy, 0.0f);

    // valid boxes have w,h in [0,1): areas are nonnegative, no fabs needed.
    float area_p = p.z * p.w;
    float area_t = t.z * t.w;

    float iou = inter / (area_p + area_t - inter + 1e-6f);

    // sentinel rows are exactly [-1,-1,-1,-1]; uniform[0,1) data never hits -1,
    // so two components suffice to identify them.
    bool valid = !(t.z == -1.0f && t.w == -1.0f);
    if (valid) {
        lsum += iou;
        lcnt += 1.0f;
    }
}

__global__ void __launch_bounds__(NTHREADS)
iou_fused_kernel(const float4* __restrict__ pred,
                 const float4* __restrict__ truth,
                 int n, float* __restrict__ out, int out_size) {
    float lsum = 0.0f;
    float lcnt = 0.0f;

    int tid = blockIdx.x * NTHREADS + threadIdx.x;
    int S = gridDim.x * NTHREADS;

    int i = tid;
    // x4 unroll, all 8 LDG.128 batched before compute -> MLP_p1 = 8.
    for (; i + 3 * S < n; i += 4 * S) {
        float4 p0 = __ldcs(pred + i);
        float4 p1 = __ldcs(pred + i + S);
        float4 p2 = __ldcs(pred + i + 2 * S);
        float4 p3 = __ldcs(pred + i + 3 * S);
        float4 t0 = __ldcs(truth + i);
        float4 t1 = __ldcs(truth + i + S);
        float4 t2 = __ldcs(truth + i + 2 * S);
        float4 t3 = __ldcs(truth + i + 3 * S);
        iou_accum(p0, t0, lsum, lcnt);
        iou_accum(p1, t1, lsum, lcnt);
        iou_accum(p2, t2, lsum, lcnt);
        iou_accum(p3, t3, lsum, lcnt);
    }
    for (; i < n; i += S) {
        float4 p = __ldcs(pred + i);
        float4 t = __ldcs(truth + i);
        iou_accum(p, t, lsum, lcnt);
    }

    // Block reduce (fp32).
    #pragma unroll
    for (int off = 16; off > 0; off >>= 1) {
        lsum += __shfl_down_sync(0xffffffffu, lsum, off);
        lcnt += __shfl_down_sync(0xffffffffu, lcnt, off);
    }
    __shared__ float ssum[NTHREADS / 32];
    __shared__ float scnt[NTHREADS / 32];
    int warp = threadIdx.x >> 5;
    int lane = threadIdx.x & 31;
    if (lane == 0) { ssum[warp] = lsum; scnt[warp] = lcnt; }
    __syncthreads();

    __shared__ bool is_last;
    if (threadIdx.x == 0) {
        float bsum = 0.0f, bcnt = 0.0f;
        #pragma unroll
        for (int w = 0; w < NTHREADS / 32; w++) {
            bsum += ssum[w];
            bcnt += scnt[w];
        }
        g_part[blockIdx.x] = make_float2(bsum, bcnt);
        __threadfence();
        unsigned int old = atomicInc(&g_count, gridDim.x - 1);
        is_last = (old == gridDim.x - 1);   // wraps to 0 -> self-resetting
    }
    __syncthreads();

    if (is_last) {
        double dsum = 0.0, dcnt = 0.0;
        for (int b = threadIdx.x; b < gridDim.x; b += NTHREADS) {
            float2 v = g_part[b];
            dsum += (double)v.x;
            dcnt += (double)v.y;
        }
        #pragma unroll
        for (int off = 16; off > 0; off >>= 1) {
            dsum += __shfl_down_sync(0xffffffffu, dsum, off);
            dcnt += __shfl_down_sync(0xffffffffu, dcnt, off);
        }
        __shared__ double dssum[NTHREADS / 32];
        __shared__ double dscnt[NTHREADS / 32];
        if (lane == 0) { dssum[warp] = dsum; dscnt[warp] = dcnt; }
        __syncthreads();
        if (threadIdx.x == 0) {
            double fsum = 0.0, fcnt = 0.0;
            #pragma unroll
            for (int w = 0; w < NTHREADS / 32; w++) {
                fsum += dssum[w];
                fcnt += dscnt[w];
            }
            float m = (fcnt > 0.0)
                        ? (float)(fsum / (fcnt < 1.0 ? 1.0 : fcnt))
                        : 0.0f;
            for (int k = 0; k < out_size; k++) out[k] = m;
        }
    }
}

extern "C" void kernel_launch(void* const* d_in, const int* in_sizes, int n_in,
                              void* d_out, int out_size) {
    const float4* pred  = (const float4*)d_in[0];
    const float4* truth = (const float4*)d_in[1];
    int n = in_sizes[0] / 4;   // number of boxes (float4 elements)

    int blocks = GRID_BLOCKS;
    int needed = (n + NTHREADS - 1) / NTHREADS;
    if (blocks > needed) blocks = needed;
    if (blocks > MAX_BLOCKS) blocks = MAX_BLOCKS;

    iou_fused_kernel<<<blocks, NTHREADS>>>(pred, truth, n,
                                           (float*)d_out, out_size);
}

// round 5
// speedup vs baseline: 1.0371x; 1.0371x over previous
#include <cuda_runtime.h>

#define MAX_BLOCKS 4096
#define NTHREADS 256
#define GRID_BLOCKS (148 * 16)

// Per-block partials {iou_sum, valid_cnt}; overwritten every launch.
__device__ float2 g_part[MAX_BLOCKS];
// Completion counter; atomicInc wraps to 0 after the last block -> self-resetting.
__device__ unsigned int g_count;

__device__ __forceinline__ void iou_accum(const float4 p, const float4 t,
                                          float& lsum, float& lcnt) {
    float phw = p.z * 0.5f, phh = p.w * 0.5f;
    float thw = t.z * 0.5f, thh = t.w * 0.5f;

    float ix = fminf(p.x + phw, t.x + thw) - fmaxf(p.x - phw, t.x - thw);
    float iy = fminf(p.y + phh, t.y + thh) - fmaxf(p.y - phh, t.y - thh);
    float inter = fmaxf(ix, 0.0f) * fmaxf(iy, 0.0f);

    // valid boxes have w,h >= 0 -> areas nonnegative, no fabs needed.
    float area_p = p.z * p.w;
    float area_t = t.z * t.w;

    float iou = inter / (area_p + area_t - inter + 1e-6f);

    // sentinel rows are exactly [-1,-1,-1,-1]; real data never hits -1.
    bool valid = !(t.z == -1.0f && t.w == -1.0f);
    if (valid) {
        lsum += iou;
        lcnt += 1.0f;
    }
}

__global__ void __launch_bounds__(NTHREADS)
iou_fused_kernel(const float4* __restrict__ pred,
                 const float4* __restrict__ truth,
                 int n, float* __restrict__ out, int out_size) {
    float lsum = 0.0f;
    float lcnt = 0.0f;

    int tid = blockIdx.x * NTHREADS + threadIdx.x;
    int S = gridDim.x * NTHREADS;

    // Default-cached loads (__ldg). R3/R4 showed __ldcs pins the stream at
    // ~5.1 TB/s; R1's __ldg mainloop ran ~6.1 TB/s.
    #pragma unroll 4
    for (int i = tid; i < n; i += S) {
        float4 p = __ldg(pred + i);
        float4 t = __ldg(truth + i);
        iou_accum(p, t, lsum, lcnt);
    }

    // Block reduce (fp32).
    #pragma unroll
    for (int off = 16; off > 0; off >>= 1) {
        lsum += __shfl_down_sync(0xffffffffu, lsum, off);
        lcnt += __shfl_down_sync(0xffffffffu, lcnt, off);
    }
    __shared__ float ssum[NTHREADS / 32];
    __shared__ float scnt[NTHREADS / 32];
    int warp = threadIdx.x >> 5;
    int lane = threadIdx.x & 31;
    if (lane == 0) { ssum[warp] = lsum; scnt[warp] = lcnt; }
    __syncthreads();

    __shared__ bool is_last;
    if (threadIdx.x == 0) {
        float bsum = 0.0f, bcnt = 0.0f;
        #pragma unroll
        for (int w = 0; w < NTHREADS / 32; w++) {
            bsum += ssum[w];
            bcnt += scnt[w];
        }
        g_part[blockIdx.x] = make_float2(bsum, bcnt);
        __threadfence();
        unsigned int old = atomicInc(&g_count, gridDim.x - 1);
        is_last = (old == gridDim.x - 1);   // wraps to 0 -> self-resetting
    }
    __syncthreads();

    if (is_last) {
        double dsum = 0.0, dcnt = 0.0;
        for (int b = threadIdx.x; b < gridDim.x; b += NTHREADS) {
            float2 v = g_part[b];
            dsum += (double)v.x;
            dcnt += (double)v.y;
        }
        #pragma unroll
        for (int off = 16; off > 0; off >>= 1) {
            dsum += __shfl_down_sync(0xffffffffu, dsum, off);
            dcnt += __shfl_down_sync(0xffffffffu, dcnt, off);
        }
        __shared__ double dssum[NTHREADS / 32];
        __shared__ double dscnt[NTHREADS / 32];
        if (lane == 0) { dssum[warp] = dsum; dscnt[warp] = dcnt; }
        __syncthreads();
        if (threadIdx.x == 0) {
            double fsum = 0.0, fcnt = 0.0;
            #pragma unroll
            for (int w = 0; w < NTHREADS / 32; w++) {
                fsum += dssum[w];
                fcnt += dscnt[w];
            }
            float m = (fcnt > 0.0)
                        ? (float)(fsum / (fcnt < 1.0 ? 1.0 : fcnt))
                        : 0.0f;
            for (int k = 0; k < out_size; k++) out[k] = m;
        }
    }
}

extern "C" void kernel_launch(void* const* d_in, const int* in_sizes, int n_in,
                              void* d_out, int out_size) {
    const float4* pred  = (const float4*)d_in[0];
    const float4* truth = (const float4*)d_in[1];
    int n = in_sizes[0] / 4;   // number of boxes (float4 elements)

    int blocks = GRID_BLOCKS;
    int needed = (n + NTHREADS - 1) / NTHREADS;
    if (blocks > needed) blocks = needed;
    if (blocks > MAX_BLOCKS) blocks = MAX_BLOCKS;

    iou_fused_kernel<<<blocks, NTHREADS>>>(pred, truth, n,
                                           (float*)d_out, out_size);
}